// round 1
// baseline (speedup 1.0000x reference)
#include <cuda_runtime.h>
#include <math_constants.h>

// Problem constants
#define Bz 8
#define Cc 64
#define Nn 2048
#define Mm 2048
#define KTH 613            // index of (tgt_K)-th smallest, tgt_K = int(2048*0.3) = 614

// Output layout: concat(src_corr[B,3,N], src_weight[B,N], mask_src[B,N,1], mask_tgt[B,1,M]) as float32
#define OFF_CORR 0
#define OFF_SW   (Bz*3*Nn)               // 49152
#define OFF_MS   (OFF_SW + Bz*Nn)        // 65536
#define OFF_MT   (OFF_MS + Bz*Nn)        // 81920

// ---------------- scratch (static device memory; no allocs allowed) ----------------
__device__ float g_pd[(size_t)Bz*Nn*Mm];     // 134 MB
__device__ float g_xx[Bz*Nn];
__device__ float g_yy[Bz*Mm];
__device__ float g_rowmax[Bz*Nn];
__device__ float g_rowinv[Bz*Nn];
__device__ float g_cmax_p[Bz*4*Mm];
__device__ float g_csum_p[Bz*4*Mm];
__device__ float g_cscore_p[Bz*4*Mm];
__device__ float g_colmax[Bz*Mm];
__device__ float g_colinv[Bz*Mm];
__device__ float g_colscore[Bz*Mm];          // scoresColSum
__device__ float g_rowscore[Bz*Nn];          // scoresRowSum
__device__ float g_colthresh[Bz];
__device__ float g_rowthresh[Bz];
__device__ float g_valsum[Bz*Nn];            // val_sum_inlier

// ---------------- block reduction helpers (blockDim.x == 256) ----------------
__device__ __forceinline__ float bsum256(float v, float* red) {
    int t = threadIdx.x;
    __syncthreads();
    red[t] = v; __syncthreads();
#pragma unroll
    for (int s = 128; s > 0; s >>= 1) {
        if (t < s) red[t] += red[t + s];
        __syncthreads();
    }
    return red[0];
}
__device__ __forceinline__ float bmax256(float v, float* red) {
    int t = threadIdx.x;
    __syncthreads();
    red[t] = v; __syncthreads();
#pragma unroll
    for (int s = 128; s > 0; s >>= 1) {
        if (t < s) red[t] = fmaxf(red[t], red[t + s]);
        __syncthreads();
    }
    return red[0];
}

// ---------------- K0: squared norms xx[b,n] / yy[b,m] ----------------
__global__ void k_sq(const float* __restrict__ A, int cols, int which) {
    int idx = blockIdx.x * 256 + threadIdx.x;
    if (idx >= Bz * cols) return;
    int b = idx / cols, x = idx % cols;
    const float* p = A + (size_t)b * Cc * cols + x;
    float s = 0.f;
#pragma unroll
    for (int c = 0; c < Cc; c++) { float v = p[(size_t)c * cols]; s += v * v; }
    float* o = which ? g_yy : g_xx;
    o[idx] = s;
}

// ---------------- K1: pd = 2*A^T B - xx - yy  (64x64 output tile / block) ----------------
__global__ void k_gemm(const float* __restrict__ A, const float* __restrict__ Bt) {
    int b = blockIdx.z, n0 = blockIdx.y * 64, m0 = blockIdx.x * 64;
    __shared__ float As[64][64];   // [c][n]
    __shared__ float Bs[64][64];   // [c][m]
    const float* Ab = A  + (size_t)b * Cc * Nn + n0;
    const float* Bb = Bt + (size_t)b * Cc * Mm + m0;
    int t = threadIdx.x;
    int nc = t & 63, c0 = t >> 6;  // 256 threads: 16 rows of c each
#pragma unroll
    for (int i = 0; i < 16; i++) {
        int c = c0 + i * 4;
        As[c][nc] = Ab[(size_t)c * Nn + nc];
        Bs[c][nc] = Bb[(size_t)c * Mm + nc];
    }
    __syncthreads();
    int tx = t & 15, ty = t >> 4;
    float acc[4][4];
#pragma unroll
    for (int i = 0; i < 4; i++)
#pragma unroll
        for (int j = 0; j < 4; j++) acc[i][j] = 0.f;
#pragma unroll
    for (int c = 0; c < 64; c++) {
        float a[4], bv[4];
#pragma unroll
        for (int i = 0; i < 4; i++) { a[i] = As[c][ty*4 + i]; bv[i] = Bs[c][tx*4 + i]; }
#pragma unroll
        for (int i = 0; i < 4; i++)
#pragma unroll
            for (int j = 0; j < 4; j++) acc[i][j] += a[i] * bv[j];
    }
    int mbase = m0 + tx * 4;
    float y0 = g_yy[b*Mm + mbase + 0];
    float y1 = g_yy[b*Mm + mbase + 1];
    float y2 = g_yy[b*Mm + mbase + 2];
    float y3 = g_yy[b*Mm + mbase + 3];
#pragma unroll
    for (int i = 0; i < 4; i++) {
        int n = n0 + ty * 4 + i;
        float x = g_xx[b*Nn + n];
        float4 o;
        o.x = 2.f * acc[i][0] - x - y0;
        o.y = 2.f * acc[i][1] - x - y1;
        o.z = 2.f * acc[i][2] - x - y2;
        o.w = 2.f * acc[i][3] - x - y3;
        *(float4*)&g_pd[((size_t)b * Nn + n) * Mm + mbase] = o;
    }
}

// ---------------- K2: per-row (axis=2) softmax stats: rowmax, 1/rowsumexp ----------------
__global__ void k_rowstats() {
    int n = blockIdx.x, b = blockIdx.y;
    const float* row = g_pd + ((size_t)b * Nn + n) * Mm;
    __shared__ float red[256];
    int t = threadIdx.x;
    float v[8];
#pragma unroll
    for (int i = 0; i < 8; i++) v[i] = row[t + i * 256];
    float mx = v[0];
#pragma unroll
    for (int i = 1; i < 8; i++) mx = fmaxf(mx, v[i]);
    mx = bmax256(mx, red);
    float s = 0.f;
#pragma unroll
    for (int i = 0; i < 8; i++) s += expf(v[i] - mx);
    s = bsum256(s, red);
    if (t == 0) { g_rowmax[b*Nn + n] = mx; g_rowinv[b*Nn + n] = 1.f / s; }
}

// ---------------- K3: per-column partials over n-chunks of 512 ----------------
// computes online (colmax, colsumexp) partials AND scoresColSum partial
__global__ void k_colpart() {
    int m = blockIdx.x * 128 + threadIdx.x;
    int chunk = blockIdx.y, b = blockIdx.z;
    const float* base = g_pd + (size_t)b * Nn * Mm + m;
    const float* rm = g_rowmax + b * Nn;
    const float* ri = g_rowinv + b * Nn;
    float mx = -CUDART_INF_F, s = 0.f, csc = 0.f;
    int n0 = chunk * 512;
    for (int n = n0; n < n0 + 512; n++) {
        float p = base[(size_t)n * Mm];
        csc += expf(p - rm[n]) * ri[n];
        if (p <= mx) {
            s += expf(p - mx);
        } else {
            s = s * expf(mx - p) + 1.f;
            mx = p;
        }
    }
    int o = (b * 4 + chunk) * Mm + m;
    g_cmax_p[o] = mx; g_csum_p[o] = s; g_cscore_p[o] = csc;
}

// ---------------- K3b: combine column partials ----------------
__global__ void k_colcombine() {
    int idx = blockIdx.x * 256 + threadIdx.x;
    if (idx >= Bz * Mm) return;
    int b = idx / Mm, m = idx % Mm;
    float mx = -CUDART_INF_F;
#pragma unroll
    for (int c = 0; c < 4; c++) mx = fmaxf(mx, g_cmax_p[(b*4 + c)*Mm + m]);
    float s = 0.f, csc = 0.f;
#pragma unroll
    for (int c = 0; c < 4; c++) {
        int o = (b*4 + c)*Mm + m;
        s   += g_csum_p[o] * expf(g_cmax_p[o] - mx);
        csc += g_cscore_p[o];
    }
    g_colmax[idx] = mx; g_colinv[idx] = 1.f / s; g_colscore[idx] = csc;
}

// ---------------- K4: scoresRowSum[b,n] = sum_m colsoftmax(pd)[n,m] ----------------
__global__ void k_rowscore_k() {
    int n = blockIdx.x, b = blockIdx.y;
    const float* row = g_pd + ((size_t)b * Nn + n) * Mm;
    __shared__ float red[256];
    float acc = 0.f;
    for (int m = threadIdx.x; m < Mm; m += 256)
        acc += expf(row[m] - g_colmax[b*Mm + m]) * g_colinv[b*Mm + m];
    acc = bsum256(acc, red);
    if (threadIdx.x == 0) g_rowscore[b*Nn + n] = acc;
}

// ---------------- K5: exact k-th smallest via in-smem bitonic sort ----------------
__global__ void k_thresh() {
    int b = blockIdx.x >> 1, which = blockIdx.x & 1;
    const float* src = which ? (g_rowscore + b * Nn) : (g_colscore + b * Mm);
    __shared__ float d[2048];
    int t = threadIdx.x;  // 1024
    d[t] = src[t]; d[t + 1024] = src[t + 1024];
    __syncthreads();
    for (int k = 2; k <= 2048; k <<= 1) {
        for (int j = k >> 1; j > 0; j >>= 1) {
            for (int i = t; i < 2048; i += 1024) {
                int l = i ^ j;
                if (l > i) {
                    bool up = ((i & k) == 0);
                    float a = d[i], c = d[l];
                    if ((a > c) == up) { d[i] = c; d[l] = a; }
                }
            }
            __syncthreads();
        }
    }
    if (t == 0) {
        if (which) g_rowthresh[b] = d[KTH];
        else       g_colthresh[b] = d[KTH];
    }
}

// ---------------- K6: final per-row pass: masks, sparse weights, src_corr ----------------
__global__ void k_final(const float* __restrict__ tgt, float* __restrict__ out) {
    int n = blockIdx.x, b = blockIdx.y;
    __shared__ float sv[Mm];
    __shared__ float red[256];
    int t = threadIdx.x;
    const float* row = g_pd + ((size_t)b * Nn + n) * Mm;
    float rm = g_rowmax[b*Nn + n], ri = g_rowinv[b*Nn + n];

    // scoresSoftCol row; topk (K=1) = row max of these same floats
    float lmax = 0.f;
    for (int m = t; m < Mm; m += 256) {
        float s = expf(row[m] - rm) * ri;
        sv[m] = s;
        lmax = fmaxf(lmax, s);
    }
    float topk = bmax256(lmax, red);

    float maskSrc = (g_rowscore[b*Nn + n] < g_rowthresh[b]) ? 1.f : 0.f;
    float cth = g_colthresh[b];

    // torch precedence: new_mask = (outlier_float + s) < topk ; w = new_mask ? 0 : s
    float lsum = 0.f;
    for (int m = t; m < Mm; m += 256) {
        float o = maskSrc;
        if (o == 0.f) o = (g_colscore[b*Mm + m] < cth) ? 1.f : 0.f;
        float s = sv[m];
        float w = ((o + s) < topk) ? 0.f : s;
        sv[m] = w;
        lsum += w;
    }
    float cs = bsum256(lsum, red);
    cs = (cs < 1e-5f) ? 1e-5f : cs;

    const float* tg = tgt + (size_t)b * 3 * Mm;
    float a0 = 0.f, a1 = 0.f, a2 = 0.f, avs = 0.f;
    for (int m = t; m < Mm; m += 256) {
        float ww = sv[m] / cs;
        avs += ww;
        a0 += tg[m]          * ww;
        a1 += tg[Mm + m]     * ww;
        a2 += tg[2*Mm + m]   * ww;
    }
    a0  = bsum256(a0,  red);
    a1  = bsum256(a1,  red);
    a2  = bsum256(a2,  red);
    avs = bsum256(avs, red);
    if (t == 0) {
        out[OFF_CORR + (size_t)b*3*Nn + 0*Nn + n] = a0;
        out[OFF_CORR + (size_t)b*3*Nn + 1*Nn + n] = a1;
        out[OFF_CORR + (size_t)b*3*Nn + 2*Nn + n] = a2;
        g_valsum[b*Nn + n] = (maskSrc != 0.f) ? 0.f : avs;
        out[OFF_MS + b*Nn + n] = maskSrc;
    }
}

// ---------------- K7: src_weight = val_sum_inlier / sum ----------------
__global__ void k_srcweight(float* __restrict__ out) {
    int b = blockIdx.x, t = threadIdx.x;  // 1024
    __shared__ float red[1024];
    float v0 = g_valsum[b*Nn + t];
    float v1 = g_valsum[b*Nn + t + 1024];
    red[t] = v0 + v1; __syncthreads();
#pragma unroll
    for (int s = 512; s > 0; s >>= 1) {
        if (t < s) red[t] += red[t + s];
        __syncthreads();
    }
    float tot = red[0];
    out[OFF_SW + b*Nn + t]        = v0 / tot;
    out[OFF_SW + b*Nn + t + 1024] = v1 / tot;
}

// ---------------- K8: mask_tgt output ----------------
__global__ void k_masktgt(float* __restrict__ out) {
    int idx = blockIdx.x * 256 + threadIdx.x;
    if (idx >= Bz * Mm) return;
    int b = idx / Mm;
    out[OFF_MT + idx] = (g_colscore[idx] < g_colthresh[b]) ? 1.f : 0.f;
}

// ---------------- launch ----------------
extern "C" void kernel_launch(void* const* d_in, const int* in_sizes, int n_in,
                              void* d_out, int out_size) {
    const float* src_emb = (const float*)d_in[0];   // [B,C,N]
    const float* tgt_emb = (const float*)d_in[1];   // [B,C,M]
    // d_in[2] = src [B,3,N] -- unused by reference
    const float* tgt     = (const float*)d_in[3];   // [B,3,M]
    float* out = (float*)d_out;

    k_sq<<<(Bz*Nn + 255)/256, 256>>>(src_emb, Nn, 0);
    k_sq<<<(Bz*Mm + 255)/256, 256>>>(tgt_emb, Mm, 1);
    k_gemm<<<dim3(Mm/64, Nn/64, Bz), 256>>>(src_emb, tgt_emb);
    k_rowstats<<<dim3(Nn, Bz), 256>>>();
    k_colpart<<<dim3(Mm/128, 4, Bz), 128>>>();
    k_colcombine<<<(Bz*Mm + 255)/256, 256>>>();
    k_rowscore_k<<<dim3(Nn, Bz), 256>>>();
    k_thresh<<<Bz*2, 1024>>>();
    k_final<<<dim3(Nn, Bz), 256>>>(tgt, out);
    k_srcweight<<<Bz, 1024>>>(out);
    k_masktgt<<<(Bz*Mm + 255)/256, 256>>>(out);
}

// round 13
// speedup vs baseline: 1.6617x; 1.6617x over previous
#include <cuda_runtime.h>
#include <math_constants.h>

#define Bz 8
#define Cc 64
#define Nn 2048
#define Mm 2048
#define KTH 613            // index of (int(2048*0.3))-th smallest

#define OFF_CORR 0
#define OFF_SW   (Bz*3*Nn)
#define OFF_MS   (OFF_SW + Bz*Nn)
#define OFF_MT   (OFF_MS + Bz*Nn)

// ---------------- scratch ----------------
__device__ __align__(16) float g_pd[(size_t)Bz*Nn*Mm];   // raw pd, 134 MB (always representable)
__device__ float g_xx[Bz*Nn];
__device__ float g_yy[Bz*Mm];
__device__ float g_rmax_p[(size_t)Bz*16*Nn];   // row-max partials [b][mt][n]
__device__ float g_cmax_p[(size_t)Bz*16*Mm];   // col-max partials [b][nt128][m]
__device__ float g_rowmax[Bz*Nn];
__device__ float g_colmax[Bz*Mm];
__device__ float g_rsum_p[(size_t)Bz*16*Nn];   // rowsum partials [b][mt][n]
__device__ float g_csum_p[(size_t)Bz*32*Mm];   // colsum partials [b][nt64][m]
__device__ float g_rowinv[Bz*Nn];              // 1/rowsum; also == topk (K=1)
__device__ float g_colinv[Bz*Mm];
__device__ float g_rs_p[(size_t)Bz*16*Nn];     // rowScore partials [b][mt][n]
__device__ float g_cs_p[(size_t)Bz*32*Mm];     // colScore partials [b][nt64][m]
__device__ float g_rowscore[Bz*Nn];
__device__ __align__(16) float g_colscore[Bz*Mm];
__device__ float g_rowth[Bz], g_colth[Bz];
__device__ float g_valsum[Bz*Nn];

// ---------------- block reductions (blockDim.x == 256) ----------------
__device__ __forceinline__ float bsum256(float v, float* red) {
    int t = threadIdx.x;
    __syncthreads();
    red[t] = v; __syncthreads();
#pragma unroll
    for (int s = 128; s > 0; s >>= 1) {
        if (t < s) red[t] += red[t + s];
        __syncthreads();
    }
    return red[0];
}

// ---------------- K0: squared norms ----------------
__global__ void k_sq(const float* __restrict__ A, int cols, int which) {
    int idx = blockIdx.x * 256 + threadIdx.x;
    if (idx >= Bz * cols) return;
    int b = idx / cols, x = idx % cols;
    const float* p = A + (size_t)b * Cc * cols + x;
    float s = 0.f;
#pragma unroll
    for (int c = 0; c < Cc; c++) { float v = p[(size_t)c * cols]; s += v * v; }
    (which ? g_yy : g_xx)[idx] = s;
}

// ---------------- K1: GEMM 128x128 tile, 8x8/thread; store pd + row/col max partials ----------------
__global__ __launch_bounds__(256) void k_gemm(const float* __restrict__ A, const float* __restrict__ Bt) {
    __shared__ float As[32][128];
    __shared__ float Bs[32][128];
    __shared__ float rbuf[128][17];
    int b = blockIdx.z;
    int n0 = blockIdx.y * 128, m0 = blockIdx.x * 128;
    const float* Ab = A  + (size_t)b * Cc * Nn + n0;
    const float* Bb = Bt + (size_t)b * Cc * Mm + m0;
    int t = threadIdx.x;
    int tx = t & 15, ty = t >> 4;

    __align__(16) float acc[8][8];
#pragma unroll
    for (int i = 0; i < 8; i++)
#pragma unroll
        for (int j = 0; j < 8; j++) acc[i][j] = 0.f;

#pragma unroll
    for (int ks = 0; ks < 64; ks += 32) {
#pragma unroll
        for (int k = 0; k < 4; k++) {
            int f = t + k * 256;           // 0..1023
            int c = f >> 5;                // 0..31
            int p = (f & 31) << 2;         // 0..124
            float4 av  = *(const float4*)&Ab[(size_t)(ks + c) * Nn + p];
            float4 bvv = *(const float4*)&Bb[(size_t)(ks + c) * Mm + p];
            As[c][p] = av.x; As[c][p+1] = av.y; As[c][p+2] = av.z; As[c][p+3] = av.w;
            Bs[c][p] = bvv.x; Bs[c][p+1] = bvv.y; Bs[c][p+2] = bvv.z; Bs[c][p+3] = bvv.w;
        }
        __syncthreads();
#pragma unroll
        for (int c = 0; c < 32; c++) {
            float a[8], bv[8];
#pragma unroll
            for (int i = 0; i < 8; i++) { a[i] = As[c][ty * 8 + i]; bv[i] = Bs[c][tx * 8 + i]; }
#pragma unroll
            for (int i = 0; i < 8; i++)
#pragma unroll
                for (int j = 0; j < 8; j++) acc[i][j] += a[i] * bv[j];
        }
        __syncthreads();
    }

    float xs[8], ys[8];
#pragma unroll
    for (int i = 0; i < 8; i++) xs[i] = g_xx[b * Nn + n0 + ty * 8 + i];
#pragma unroll
    for (int j = 0; j < 8; j++) ys[j] = g_yy[b * Mm + m0 + tx * 8 + j];

    // pd = 2*acc - xx - yy (stored raw; exp happens later with max subtraction)
#pragma unroll
    for (int i = 0; i < 8; i++) {
#pragma unroll
        for (int j = 0; j < 8; j++) acc[i][j] = 2.f * acc[i][j] - xs[i] - ys[j];
        size_t off = ((size_t)b * Nn + n0 + ty * 8 + i) * Mm + m0 + tx * 8;
        *(float4*)&g_pd[off]     = *(float4*)&acc[i][0];
        *(float4*)&g_pd[off + 4] = *(float4*)&acc[i][4];
    }

    // row-max partials (max over this tile's 128 m)
#pragma unroll
    for (int i = 0; i < 8; i++) {
        float mx = acc[i][0];
#pragma unroll
        for (int j = 1; j < 8; j++) mx = fmaxf(mx, acc[i][j]);
        rbuf[ty * 8 + i][tx] = mx;
    }
    __syncthreads();
    if (t < 128) {
        float mx = rbuf[t][0];
#pragma unroll
        for (int k = 1; k < 16; k++) mx = fmaxf(mx, rbuf[t][k]);
        g_rmax_p[((size_t)b * 16 + blockIdx.x) * Nn + n0 + t] = mx;
    }
    __syncthreads();
    // col-max partials (max over this tile's 128 n)
#pragma unroll
    for (int j = 0; j < 8; j++) {
        float mx = acc[0][j];
#pragma unroll
        for (int i = 1; i < 8; i++) mx = fmaxf(mx, acc[i][j]);
        rbuf[tx * 8 + j][ty] = mx;
    }
    __syncthreads();
    if (t < 128) {
        float mx = rbuf[t][0];
#pragma unroll
        for (int k = 1; k < 16; k++) mx = fmaxf(mx, rbuf[t][k]);
        g_cmax_p[((size_t)b * 16 + blockIdx.y) * Mm + m0 + t] = mx;
    }
}

// ---------------- K2: combine max partials ----------------
__global__ void k_combine1() {
    int idx = blockIdx.x * 256 + threadIdx.x;
    if (idx < Bz * Nn) {
        int b = idx / Nn, n = idx % Nn;
        float mx = -CUDART_INF_F;
#pragma unroll
        for (int k = 0; k < 16; k++) mx = fmaxf(mx, g_rmax_p[((size_t)b * 16 + k) * Nn + n]);
        g_rowmax[idx] = mx;
    } else if (idx < 2 * Bz * Nn) {
        int j = idx - Bz * Nn;
        int b = j / Mm, m = j % Mm;
        float mx = -CUDART_INF_F;
#pragma unroll
        for (int k = 0; k < 16; k++) mx = fmaxf(mx, g_cmax_p[((size_t)b * 16 + k) * Mm + m]);
        g_colmax[j] = mx;
    }
}

// ---------------- K3: one tiled pass -> rowsum & colsum partials (max-subtracted exp) ----------------
__global__ __launch_bounds__(256) void k_sums() {
    __shared__ float Es[64][133];   // 133 stride: conflict-free row reads (gcd(133,32)=1 on 4B banks)
    __shared__ float rmx[64];
    __shared__ float cmx[128];
    int b = blockIdx.z, mt = blockIdx.x, nt = blockIdx.y;
    int n0 = nt * 64, m0 = mt * 128;
    int t = threadIdx.x;
    const float* base = g_pd + ((size_t)b * Nn + n0) * Mm + m0;
#pragma unroll
    for (int k = 0; k < 8; k++) {
        int f = t + k * 256;
        int r = f >> 5, p = (f & 31) << 2;
        float4 v = *(const float4*)&base[(size_t)r * Mm + p];
        Es[r][p] = v.x; Es[r][p+1] = v.y; Es[r][p+2] = v.z; Es[r][p+3] = v.w;
    }
    if (t < 128) cmx[t] = g_colmax[b * Mm + m0 + t];
    else if (t < 192) rmx[t - 128] = g_rowmax[b * Nn + n0 + (t - 128)];
    __syncthreads();
    if (t < 64) {
        float mv = rmx[t];
        float s = 0.f;
#pragma unroll 8
        for (int j = 0; j < 128; j++) s += expf(Es[t][j] - mv);
        g_rsum_p[((size_t)b * 16 + mt) * Nn + n0 + t] = s;
    } else if (t < 192) {
        int c = t - 64;
        float mv = cmx[c];
        float s = 0.f;
#pragma unroll 8
        for (int i = 0; i < 64; i++) s += expf(Es[i][c] - mv);
        g_csum_p[((size_t)b * 32 + nt) * Mm + m0 + c] = s;
    }
}

// ---------------- K4: combine sum partials -> rowinv, colinv ----------------
__global__ void k_combine2() {
    int idx = blockIdx.x * 256 + threadIdx.x;
    if (idx < Bz * Nn) {
        int b = idx / Nn, n = idx % Nn;
        float s = 0.f;
#pragma unroll
        for (int k = 0; k < 16; k++) s += g_rsum_p[((size_t)b * 16 + k) * Nn + n];
        g_rowinv[idx] = 1.f / s;     // rowsum >= 1 (contains exp(0))
    } else if (idx < 2 * Bz * Nn) {
        int j = idx - Bz * Nn;
        int b = j / Mm, m = j % Mm;
        float s = 0.f;
#pragma unroll
        for (int k = 0; k < 32; k++) s += g_csum_p[((size_t)b * 32 + k) * Mm + m];
        g_colinv[j] = 1.f / s;
    }
}

// ---------------- K5: tiled pass -> rowScore & colScore partials ----------------
__global__ __launch_bounds__(256) void k_scores() {
    __shared__ float Es[64][133];
    __shared__ float rmx[64], ri[64];
    __shared__ float cmx[128], ci[128];
    int b = blockIdx.z, mt = blockIdx.x, nt = blockIdx.y;
    int n0 = nt * 64, m0 = mt * 128;
    int t = threadIdx.x;
    const float* base = g_pd + ((size_t)b * Nn + n0) * Mm + m0;
#pragma unroll
    for (int k = 0; k < 8; k++) {
        int f = t + k * 256;
        int r = f >> 5, p = (f & 31) << 2;
        float4 v = *(const float4*)&base[(size_t)r * Mm + p];
        Es[r][p] = v.x; Es[r][p+1] = v.y; Es[r][p+2] = v.z; Es[r][p+3] = v.w;
    }
    if (t < 128) { cmx[t] = g_colmax[b * Mm + m0 + t]; ci[t] = g_colinv[b * Mm + m0 + t]; }
    else if (t < 192) { int r = t - 128; rmx[r] = g_rowmax[b * Nn + n0 + r]; ri[r] = g_rowinv[b * Nn + n0 + r]; }
    __syncthreads();
    if (t < 64) {
        // scoresRowSum_n partial = sum_m colsoftmax = sum_m exp(pd - colmax_m)*colinv_m
        float s = 0.f;
#pragma unroll 8
        for (int j = 0; j < 128; j++) s += expf(Es[t][j] - cmx[j]) * ci[j];
        g_rs_p[((size_t)b * 16 + mt) * Nn + n0 + t] = s;
    } else if (t < 192) {
        // scoresColSum_m partial = sum_n rowsoftmax = sum_n exp(pd - rowmax_n)*rowinv_n
        int c = t - 64;
        float s = 0.f;
#pragma unroll 8
        for (int i = 0; i < 64; i++) s += expf(Es[i][c] - rmx[i]) * ri[i];
        g_cs_p[((size_t)b * 32 + nt) * Mm + m0 + c] = s;
    }
}

// ---------------- K6: combine score partials + exact kth smallest (bitonic) ----------------
__global__ void k_thresh() {
    int b = blockIdx.x >> 1, which = blockIdx.x & 1;
    __shared__ float d[2048];
    int t = threadIdx.x;  // 1024
    if (which == 0) {
        for (int i = t; i < 2048; i += 1024) {
            float s = 0.f;
#pragma unroll
            for (int k = 0; k < 32; k++) s += g_cs_p[((size_t)b * 32 + k) * Mm + i];
            g_colscore[b * Mm + i] = s; d[i] = s;
        }
    } else {
        for (int i = t; i < 2048; i += 1024) {
            float s = 0.f;
#pragma unroll
            for (int k = 0; k < 16; k++) s += g_rs_p[((size_t)b * 16 + k) * Nn + i];
            g_rowscore[b * Nn + i] = s; d[i] = s;
        }
    }
    __syncthreads();
    for (int k = 2; k <= 2048; k <<= 1) {
        for (int j = k >> 1; j > 0; j >>= 1) {
            for (int i = t; i < 2048; i += 1024) {
                int l = i ^ j;
                if (l > i) {
                    bool up = ((i & k) == 0);
                    float a = d[i], c = d[l];
                    if ((a > c) == up) { d[i] = c; d[l] = a; }
                }
            }
            __syncthreads();
        }
    }
    if (t == 0) {
        if (which) g_rowth[b] = d[KTH];
        else       g_colth[b] = d[KTH];
    }
}

// ---------------- K7: final pass: masks, sparse weights, src_corr ----------------
__global__ __launch_bounds__(256) void k_final(const float* __restrict__ tgt, float* __restrict__ out) {
    int n = blockIdx.x, b = blockIdx.y;
    __shared__ float sv[Mm];
    __shared__ float red[256];
    int t = threadIdx.x;
    const float* row = g_pd + ((size_t)b * Nn + n) * Mm;
    const float* csc = g_colscore + b * Mm;
    float rmax = g_rowmax[b * Nn + n];
    float ri   = g_rowinv[b * Nn + n];
    float topk = ri;   // K=1: max_m s = exp(rowmax-rowmax)*rowinv = rowinv exactly
    float maskSrc = (g_rowscore[b * Nn + n] < g_rowth[b]) ? 1.f : 0.f;
    float cth = g_colth[b];

    float lsum = 0.f;
#pragma unroll
    for (int k = 0; k < 2; k++) {
        int idx = t + k * 256;
        float4 e  = *(const float4*)&row[idx * 4];
        float4 c4 = *(const float4*)&csc[idx * 4];
        float w0, w1, w2, w3;
        {
            float s = expf(e.x - rmax) * ri;
            float o = maskSrc != 0.f ? 1.f : ((c4.x < cth) ? 1.f : 0.f);
            w0 = ((o + s) < topk) ? 0.f : s;
        }
        {
            float s = expf(e.y - rmax) * ri;
            float o = maskSrc != 0.f ? 1.f : ((c4.y < cth) ? 1.f : 0.f);
            w1 = ((o + s) < topk) ? 0.f : s;
        }
        {
            float s = expf(e.z - rmax) * ri;
            float o = maskSrc != 0.f ? 1.f : ((c4.z < cth) ? 1.f : 0.f);
            w2 = ((o + s) < topk) ? 0.f : s;
        }
        {
            float s = expf(e.w - rmax) * ri;
            float o = maskSrc != 0.f ? 1.f : ((c4.w < cth) ? 1.f : 0.f);
            w3 = ((o + s) < topk) ? 0.f : s;
        }
        int m4 = idx * 4;
        sv[m4] = w0; sv[m4+1] = w1; sv[m4+2] = w2; sv[m4+3] = w3;
        lsum += (w0 + w1) + (w2 + w3);
    }
    float cs = bsum256(lsum, red);
    cs = (cs < 1e-5f) ? 1e-5f : cs;
    float inv = 1.f / cs;

    const float* tg = tgt + (size_t)b * 3 * Mm;
    float a0 = 0.f, a1 = 0.f, a2 = 0.f, avs = 0.f;
    for (int k = 0; k < 2; k++) {
        int m4 = (t + k * 256) * 4;
#pragma unroll
        for (int q = 0; q < 4; q++) {
            float w = sv[m4 + q] * inv;
            avs += w;
            a0 += tg[m4 + q]          * w;
            a1 += tg[Mm + m4 + q]     * w;
            a2 += tg[2 * Mm + m4 + q] * w;
        }
    }
    a0  = bsum256(a0,  red);
    a1  = bsum256(a1,  red);
    a2  = bsum256(a2,  red);
    avs = bsum256(avs, red);
    if (t == 0) {
        out[OFF_CORR + (size_t)b * 3 * Nn + 0 * Nn + n] = a0;
        out[OFF_CORR + (size_t)b * 3 * Nn + 1 * Nn + n] = a1;
        out[OFF_CORR + (size_t)b * 3 * Nn + 2 * Nn + n] = a2;
        g_valsum[b * Nn + n] = (maskSrc != 0.f) ? 0.f : avs;
        out[OFF_MS + b * Nn + n] = maskSrc;
    }
}

// ---------------- K8: src_weight ----------------
__global__ void k_srcweight(float* __restrict__ out) {
    int b = blockIdx.x, t = threadIdx.x;  // 1024
    __shared__ float red[1024];
    float v0 = g_valsum[b * Nn + t];
    float v1 = g_valsum[b * Nn + t + 1024];
    red[t] = v0 + v1; __syncthreads();
#pragma unroll
    for (int s = 512; s > 0; s >>= 1) {
        if (t < s) red[t] += red[t + s];
        __syncthreads();
    }
    float tot = red[0];
    out[OFF_SW + b * Nn + t]        = v0 / tot;
    out[OFF_SW + b * Nn + t + 1024] = v1 / tot;
}

// ---------------- K9: mask_tgt ----------------
__global__ void k_masktgt(float* __restrict__ out) {
    int idx = blockIdx.x * 256 + threadIdx.x;
    if (idx >= Bz * Mm) return;
    int b = idx / Mm;
    out[OFF_MT + idx] = (g_colscore[idx] < g_colth[b]) ? 1.f : 0.f;
}

// ---------------- launch ----------------
extern "C" void kernel_launch(void* const* d_in, const int* in_sizes, int n_in,
                              void* d_out, int out_size) {
    const float* src_emb = (const float*)d_in[0];
    const float* tgt_emb = (const float*)d_in[1];
    const float* tgt     = (const float*)d_in[3];
    float* out = (float*)d_out;

    k_sq<<<(Bz*Nn + 255)/256, 256>>>(src_emb, Nn, 0);
    k_sq<<<(Bz*Mm + 255)/256, 256>>>(tgt_emb, Mm, 1);
    k_gemm<<<dim3(Mm/128, Nn/128, Bz), 256>>>(src_emb, tgt_emb);
    k_combine1<<<(2*Bz*Nn + 255)/256, 256>>>();
    k_sums<<<dim3(Mm/128, Nn/64, Bz), 256>>>();
    k_combine2<<<(2*Bz*Nn + 255)/256, 256>>>();
    k_scores<<<dim3(Mm/128, Nn/64, Bz), 256>>>();
    k_thresh<<<Bz*2, 1024>>>();
    k_final<<<dim3(Nn, Bz), 256>>>(tgt, out);
    k_srcweight<<<Bz, 1024>>>(out);
    k_masktgt<<<(Bz*Mm + 255)/256, 256>>>(out);
}